// round 15
// baseline (speedup 1.0000x reference)
#include <cuda_runtime.h>
#include <math.h>

// Problem shape is fixed: N = 16384.
#define N_ELEM  16384
#define TN      256                         // tile dimension (rows=cols=threads)
#define NTILES  (N_ELEM / TN)               // 64
#define NTT     (NTILES * (NTILES + 1) / 2) // 2080 upper-triangle tiles
#define GRIDN   (NTT + 1)                   // + block 0 = B-term block
#define NBINS   8192                        // counting-sort bins for B

// Column split per tile-row: 208 cols MUFU tanh.f16x2, 48 cols FMA-pipe f16x2 poly.
#define F16_ITERS  26                       // 26 * 8 = 208 columns
#define POLY_ITERS 24                       // 24 * 2 = 48  columns
#define POLY_BASE  208

typedef unsigned int uint;

// Scratch (no cudaMalloc allowed). Counters/bins self-reset each launch.
__device__ float        g_partials[NTT];
__device__ uint         g_bins[NBINS];
__device__ float        g_sorted[N_ELEM];
__device__ double       g_Bsum;
__device__ unsigned int g_arrive = 0;       // reset by last block each launch

// ---- f16x2 helpers ---------------------------------------------------------
__device__ __forceinline__ uint cvt2h(float hi, float lo) {   // pack {lo,hi} f16x2
    uint r; asm("cvt.rn.f16x2.f32 %0, %1, %2;" : "=r"(r) : "f"(hi), "f"(lo)); return r;
}
__device__ __forceinline__ uint hsub2(uint a, uint b) {
    uint r; asm("sub.f16x2 %0, %1, %2;" : "=r"(r) : "r"(a), "r"(b)); return r;
}
__device__ __forceinline__ uint hmul2(uint a, uint b) {
    uint r; asm("mul.f16x2 %0, %1, %2;" : "=r"(r) : "r"(a), "r"(b)); return r;
}
__device__ __forceinline__ uint hadd2(uint a, uint b) {
    uint r; asm("add.f16x2 %0, %1, %2;" : "=r"(r) : "r"(a), "r"(b)); return r;
}
__device__ __forceinline__ uint hfma2(uint a, uint b, uint c) {
    uint r; asm("fma.rn.f16x2 %0, %1, %2, %3;" : "=r"(r) : "r"(a), "r"(b), "r"(c)); return r;
}
__device__ __forceinline__ uint hmin2(uint a, uint b) {
    uint r; asm("min.f16x2 %0, %1, %2;" : "=r"(r) : "r"(a), "r"(b)); return r;
}
__device__ __forceinline__ uint htanh2(uint x) {
    uint r; asm("tanh.approx.f16x2 %0, %1;" : "=r"(r) : "r"(x)); return r;
}
__device__ __forceinline__ void h2_to_f32(float& a, float& b, uint p) {
    asm("{\n\t.reg .b16 l, h;\n\tmov.b32 {l, h}, %2;\n\t"
        "cvt.f32.f16 %0, l;\n\tcvt.f32.f16 %1, h;\n\t}"
        : "=f"(a), "=f"(b) : "r"(p));
}
__device__ __forceinline__ uint  ldcg_u32(const uint* p)  { uint v;  asm volatile("ld.global.cg.u32 %0, [%1];" : "=r"(v) : "l"(p)); return v; }
__device__ __forceinline__ float ldcg_f32(const float* p) { float v; asm volatile("ld.global.cg.f32 %0, [%1];" : "=f"(v) : "l"(p)); return v; }

// ---- packed f16x2 constants (one u32 each) ----
#define MAGH   0x62006200u   // 1536.0 : magic rounder (f16 spacing=1 here)
#define C1548  0x4BBE4BBEu   // 15.484375 : clamp so n <= 15
#define ONEH   0x3C003C00u   // 1.0
#define E1N    0xB98CB98Cu   // -0.693359  2^-x Taylor
#define E2P    0x33B033B0u   //  0.240234
#define E3N    0xAB1BAB1Bu   // -0.055511
#define R0P    0x3BFF3BFFu   //  0.999512  R(q) ~ 1/(1+q), deg-4 Chebyshev
#define R1N    0xBBE3BBE3u   // -0.985840
#define R2P    0x3AFA3AFAu   //  0.872070
#define R3N    0xB857B857u   // -0.542480
#define R4P    0x31053105u   //  0.156860

// Block 0:          computes B = sum_{i<j} |t_i - t_j| exactly (to ~2e-7 rel)
//                   via 8192-bin counting sort + rank-weight formula in fp64.
// Blocks 1..NTT:    tile (I,J) of the upper triangle; accumulate ONLY the
//                   A-term  sum tanh(p_i p_j / 2) * |t_i - t_j|  (B removed
//                   from the hot loop -> FMA pipe at ~81% of MUFU duty).
// Total: S = 0.5*sum(A) + 0.5*B ;  out = -S / N^2.
__global__ __launch_bounds__(TN) void pair_tile_kernel(
    const float* __restrict__ yt, const float* __restrict__ yp,
    float* __restrict__ out)
{
    __shared__ __align__(16) uint4 sh[2 * F16_ITERS];  // f16 col stage
    __shared__ __align__(8)  uint2 sp[POLY_ITERS];     // poly col stage
    __shared__ float  red[TN / 32];
    __shared__ double dred[TN / 32];
    __shared__ uint   sscan[TN];
    __shared__ uint   swtot[TN / 32];
    __shared__ unsigned int is_last;

    const int tid  = threadIdx.x;
    const int lane = tid & 31;
    const int wid  = tid >> 5;
    const int kb   = blockIdx.x;

    if (kb == 0) {
        // ================= B-term block (counting sort + rank weights) =====
        // 1. zero bins
        for (int i = tid; i < NBINS; i += TN) g_bins[i] = 0u;
        __syncthreads();
        // 2. histogram (REDG, no return value needed)
        for (int i = tid; i < N_ELEM; i += TN) {
            int b = (int)(yt[i] * (float)NBINS);
            b = b < 0 ? 0 : (b >= NBINS ? NBINS - 1 : b);
            atomicAdd(&g_bins[b], 1u);
        }
        __syncthreads();
        // 3. exclusive prefix scan over bins (32 contiguous bins per thread)
        const int base = tid * (NBINS / TN);
        uint csum = 0;
        for (int i = 0; i < NBINS / TN; i++) csum += ldcg_u32(&g_bins[base + i]);
        sscan[tid] = csum;
        __syncthreads();
        uint v = sscan[tid];
        uint inc = v;
        #pragma unroll
        for (int o = 1; o < 32; o <<= 1) {
            uint n = __shfl_up_sync(0xFFFFFFFFu, inc, o);
            if (lane >= o) inc += n;
        }
        if (lane == 31) swtot[wid] = inc;
        __syncthreads();
        uint woff = 0;
        for (int w = 0; w < wid; w++) woff += swtot[w];
        const uint excl = woff + inc - v;
        __syncthreads();
        uint run = excl;
        for (int i = 0; i < NBINS / TN; i++) {
            uint c = ldcg_u32(&g_bins[base + i]);
            g_bins[base + i] = run;               // bin cursor = exclusive offset
            run += c;
        }
        __syncthreads();
        // 4. scatter t into bin order (within-bin order arbitrary; |dt| < 1/NBINS)
        for (int i = tid; i < N_ELEM; i += TN) {
            float t = yt[i];
            int b = (int)(t * (float)NBINS);
            b = b < 0 ? 0 : (b >= NBINS ? NBINS - 1 : b);
            uint pos = atomicAdd(&g_bins[b], 1u);
            g_sorted[pos] = t;
        }
        __syncthreads();
        // 5. B = sum_k t_(k) * (2k - (N-1)) in fp64
        double acc = 0.0;
        for (int q = tid; q < N_ELEM; q += TN) {
            float tv = ldcg_f32(&g_sorted[q]);
            acc += (double)tv * (double)(2 * q - (N_ELEM - 1));
        }
        #pragma unroll
        for (int o = 16; o > 0; o >>= 1)
            acc += __shfl_xor_sync(0xFFFFFFFFu, acc, o);
        if (lane == 0) dred[wid] = acc;
        __syncthreads();
        if (tid == 0) {
            double bt = 0.0;
            #pragma unroll
            for (int w = 0; w < TN / 32; w++) bt += dred[w];
            g_Bsum = bt;
        }
    } else {
        // ================= tile block =======================================
        const int k = kb - 1;
        // Invert linear triangular tile index k -> (I, J), I <= J.
        const float disc = 2.0f * (float)NTILES + 1.0f;
        int I = (int)((disc - sqrtf(disc * disc - 8.0f * (float)k)) * 0.5f);
        if (I < 0) I = 0;
        if (I >= NTILES) I = NTILES - 1;
        while (((I + 1) * NTILES - ((I + 1) * I) / 2) <= k) ++I;
        while ((I * NTILES - (I * (I - 1)) / 2) > k) --I;
        const int J = I + (k - (I * NTILES - (I * (I - 1)) / 2));

        // Row values for this thread.
        const int ig = I * TN + tid;
        const float ti = yt[ig];
        const float pi = yp[ig];
        const uint ti2  = cvt2h(ti, ti);
        const uint pih2 = cvt2h(0.5f * pi, 0.5f * pi);
        const float pil = pi * 1.4426950408889634f;
        const uint pil2 = cvt2h(pil, pil);

        // Stage columns.
        if (tid < POLY_BASE / 2) {                          // f16 cols 0..207
            const float2 tc = *(const float2*)(yt + J * TN + 2 * tid);
            const float2 pc = *(const float2*)(yp + J * TN + 2 * tid);
            const uint th2 = cvt2h(tc.y, tc.x);
            const uint ph2 = cvt2h(0.5f * pc.y, 0.5f * pc.x);
            uint* sw = (uint*)sh;
            const int g = tid >> 1, s = tid & 1;
            sw[4 * g + 2 * s]     = th2;
            sw[4 * g + 2 * s + 1] = ph2;
        } else if (tid < POLY_BASE / 2 + POLY_ITERS) {      // poly cols 208..255
            const int idx = tid - POLY_BASE / 2;
            const int c = J * TN + POLY_BASE + 2 * idx;
            const float2 tc = *(const float2*)(yt + c);
            const float2 pc = *(const float2*)(yp + c);
            sp[idx].x = cvt2h(tc.y, tc.x);
            sp[idx].y = cvt2h(pc.y * 1.4426950408889634f,
                              pc.x * 1.4426950408889634f);
        }
        __syncthreads();

        // A-only accumulators (signed tanh*|d| terms; <=26 per lane, f16-safe).
        uint Aa = 0u, Ab = 0u, Ac = 0u, Ad = 0u;
        uint PolyA = 0u;

#define F16_BODY(g)                                                         \
        {                                                                   \
            const uint4 w0 = sh[2 * (g)];                                   \
            const uint4 w1 = sh[2 * (g) + 1];                               \
            const uint ad_a = hsub2(ti2, w0.x) & 0x7FFF7FFFu;               \
            const uint ad_b = hsub2(ti2, w0.z) & 0x7FFF7FFFu;               \
            const uint ad_c = hsub2(ti2, w1.x) & 0x7FFF7FFFu;               \
            const uint ad_d = hsub2(ti2, w1.z) & 0x7FFF7FFFu;               \
            const uint s_a  = htanh2(hmul2(pih2, w0.y));                    \
            const uint s_b  = htanh2(hmul2(pih2, w0.w));                    \
            const uint s_c  = htanh2(hmul2(pih2, w1.y));                    \
            const uint s_d  = htanh2(hmul2(pih2, w1.w));                    \
            Aa = hfma2(s_a, ad_a, Aa);                                      \
            Ab = hfma2(s_b, ad_b, Ab);                                      \
            Ac = hfma2(s_c, ad_c, Ac);                                      \
            Ad = hfma2(s_d, ad_d, Ad);                                      \
        }

#define POLY_BODY(g)                                                        \
        {                                                                   \
            const uint2 pp = sp[g];                                         \
            const uint zs  = hmul2(pil2, pp.y);                             \
            const uint at  = hmin2(zs & 0x7FFF7FFFu, C1548);                \
            const uint m2  = hadd2(at, MAGH);                               \
            const uint nsh = (m2 & 0x000F000Fu) << 10;                      \
            const uint sb  = 0x3C003C00u - nsh;                             \
            const uint nn  = hsub2(m2, MAGH);                               \
            const uint fr  = hsub2(at, nn);                                 \
            uint P = hfma2(E3N, fr, E2P);                                   \
            P = hfma2(P, fr, E1N);                                          \
            P = hfma2(P, fr, ONEH);                                         \
            const uint q = hmul2(sb, P);                                    \
            uint R = hfma2(R4P, q, R3N);                                    \
            R = hfma2(R, q, R2P);                                           \
            R = hfma2(R, q, R1N);                                           \
            R = hfma2(R, q, R0P);                                           \
            const uint T  = hfma2(q ^ 0x80008000u, R, R);                   \
            const uint ad = hsub2(ti2, pp.x) & 0x7FFF7FFFu;                 \
            const uint sd = ad ^ (zs & 0x80008000u);                        \
            PolyA = hfma2(T, sd, PolyA);                                    \
        }

        #pragma unroll 4
        for (int g = 0; g < POLY_ITERS; g++) {
            F16_BODY(g)
            POLY_BODY(g)
        }
        #pragma unroll
        for (int g = POLY_ITERS; g < F16_ITERS; g++) {
            F16_BODY(g)
        }
#undef F16_BODY
#undef POLY_BODY

        const uint At = hadd2(hadd2(Aa, Ab), hadd2(Ac, Ad));
        float al, ah, qal, qah;
        h2_to_f32(al, ah, At);
        h2_to_f32(qal, qah, PolyA);
        float P = 0.5f * ((al + ah) + (qal + qah));
        if (I == J) P *= 0.5f;

        #pragma unroll
        for (int o = 16; o > 0; o >>= 1)
            P += __shfl_xor_sync(0xFFFFFFFFu, P, o);
        if (lane == 0) red[wid] = P;
        __syncthreads();
        if (tid == 0) {
            float s = 0.f;
            #pragma unroll
            for (int w = 0; w < TN / 32; w++) s += red[w];
            g_partials[k] = s;
        }
    }

    // Publish; last-arriving block does the (deterministic-order) final sum.
    if (tid == 0) {
        __threadfence();
        unsigned int old = atomicAdd(&g_arrive, 1u);
        is_last = (old == (unsigned)(GRIDN - 1)) ? 1u : 0u;
    }
    __syncthreads();

    if (is_last) {
        __threadfence();
        double s = 0.0;
        for (int i = tid; i < NTT; i += TN)   // fixed order
            s += (double)g_partials[i];
        #pragma unroll
        for (int o = 16; o > 0; o >>= 1)
            s += __shfl_xor_sync(0xFFFFFFFFu, s, o);
        if (lane == 0) dred[wid] = s;
        __syncthreads();
        if (tid == 0) {
            double tot = 0.0;
            #pragma unroll
            for (int w = 0; w < TN / 32; w++) tot += dred[w];
            tot += 0.5 * g_Bsum;                   // + 0.5 * sum |d|
            const double n2 = (double)N_ELEM * (double)N_ELEM;
            out[0] = (float)(-tot / n2);
            g_arrive = 0;                          // re-arm for next graph replay
        }
    }
}

extern "C" void kernel_launch(void* const* d_in, const int* in_sizes, int n_in,
                              void* d_out, int out_size)
{
    const float* yt = (const float*)d_in[0];  // y_true
    const float* yp = (const float*)d_in[1];  // y_pred
    float* out = (float*)d_out;

    pair_tile_kernel<<<GRIDN, TN>>>(yt, yp, out);
}